// round 1
// baseline (speedup 1.0000x reference)
#include <cuda_runtime.h>
#include <math.h>

#define B_  4
#define N_  2048
#define C_  1024
#define H_  16
#define D_  64
#define BH_ (B_ * H_)   // 64
#define BN_ (B_ * N_)   // 8192

// ---------------- scratch (device globals; no allocations allowed) ----------
__device__ float g_qkv[(size_t)BN_ * 3 * C_];   // [b*n][3C]
__device__ float g_q[(size_t)BH_ * D_ * N_];    // [bh][d][n]  (d-major for flash)
__device__ float g_k[(size_t)BH_ * D_ * N_];    // [bh][d][n]
__device__ float g_v[(size_t)BH_ * N_ * D_];    // [bh][n][d]
__device__ float g_att[(size_t)BN_ * C_];       // [b][n][c]

// =====================================================================
// SGEMM: C[M,N] = A[M,K] * B[N,K]^T   (both K-contiguous, fp32)
// 128x128 block, BK=8, 256 threads, 8x8 per thread, double-buffered smem
// All dims are multiples of 128/8 in this problem -> no bounds checks.
// =====================================================================
__global__ __launch_bounds__(256, 2)
void sgemm_nt(const float* __restrict__ A, const float* __restrict__ Bm,
              float* __restrict__ C, int M, int N, int K)
{
    __shared__ float As[2][8][128];
    __shared__ float Bs[2][8][128];

    const int tid = threadIdx.x;
    const int tx = tid & 15;
    const int ty = tid >> 4;
    const int bm = blockIdx.y * 128;
    const int bn = blockIdx.x * 128;

    const int sr = tid >> 1;          // row within tile (m or n)
    const int sk = (tid & 1) * 4;     // k offset

    const float* Ap = A  + (size_t)(bm + sr) * K + sk;
    const float* Bp = Bm + (size_t)(bn + sr) * K + sk;

    float acc[8][8];
#pragma unroll
    for (int i = 0; i < 8; i++)
#pragma unroll
        for (int j = 0; j < 8; j++) acc[i][j] = 0.f;

    float4 a_st = *(const float4*)Ap;
    float4 b_st = *(const float4*)Bp;

    int buf = 0;
    As[0][sk + 0][sr] = a_st.x; As[0][sk + 1][sr] = a_st.y;
    As[0][sk + 2][sr] = a_st.z; As[0][sk + 3][sr] = a_st.w;
    Bs[0][sk + 0][sr] = b_st.x; Bs[0][sk + 1][sr] = b_st.y;
    Bs[0][sk + 2][sr] = b_st.z; Bs[0][sk + 3][sr] = b_st.w;
    __syncthreads();

    const int ktiles = K >> 3;
    for (int kt = 0; kt < ktiles; kt++) {
        if (kt + 1 < ktiles) {
            a_st = *(const float4*)(Ap + (size_t)(kt + 1) * 8);
            b_st = *(const float4*)(Bp + (size_t)(kt + 1) * 8);
        }
#pragma unroll
        for (int k = 0; k < 8; k++) {
            float4 a0 = *(const float4*)&As[buf][k][ty * 4];
            float4 a1 = *(const float4*)&As[buf][k][ty * 4 + 64];
            float4 b0 = *(const float4*)&Bs[buf][k][tx * 4];
            float4 b1 = *(const float4*)&Bs[buf][k][tx * 4 + 64];
            float av[8] = {a0.x, a0.y, a0.z, a0.w, a1.x, a1.y, a1.z, a1.w};
            float bv[8] = {b0.x, b0.y, b0.z, b0.w, b1.x, b1.y, b1.z, b1.w};
#pragma unroll
            for (int i = 0; i < 8; i++)
#pragma unroll
                for (int j = 0; j < 8; j++)
                    acc[i][j] = fmaf(av[i], bv[j], acc[i][j]);
        }
        if (kt + 1 < ktiles) {
            const int nb = buf ^ 1;
            As[nb][sk + 0][sr] = a_st.x; As[nb][sk + 1][sr] = a_st.y;
            As[nb][sk + 2][sr] = a_st.z; As[nb][sk + 3][sr] = a_st.w;
            Bs[nb][sk + 0][sr] = b_st.x; Bs[nb][sk + 1][sr] = b_st.y;
            Bs[nb][sk + 2][sr] = b_st.z; Bs[nb][sk + 3][sr] = b_st.w;
            __syncthreads();
            buf = nb;
        }
    }

#pragma unroll
    for (int i = 0; i < 8; i++) {
        const int row = bm + ((i < 4) ? (ty * 4 + i) : (64 + ty * 4 + i - 4));
        float4 v0 = make_float4(acc[i][0], acc[i][1], acc[i][2], acc[i][3]);
        float4 v1 = make_float4(acc[i][4], acc[i][5], acc[i][6], acc[i][7]);
        *(float4*)&C[(size_t)row * N + bn + tx * 4]      = v0;
        *(float4*)&C[(size_t)row * N + bn + tx * 4 + 64] = v1;
    }
}

// =====================================================================
// Prep: per (b,n,h) RMSNorm (fp32) + interleaved RoPE on q,k; copy v.
// 512 threads = 16 warps, warp w = head w; lane l owns pair (2l, 2l+1).
// Writes q,k in [bh][d][n] (d-major) so flash needs no smem transposes.
// =====================================================================
__global__ void prep_kernel(const float* __restrict__ cosd,
                            const float* __restrict__ sind,
                            const float* __restrict__ qg,
                            const float* __restrict__ kg)
{
    const int bn = blockIdx.x;          // b*2048 + n
    const int n  = bn & (N_ - 1);
    const int b  = bn >> 11;
    const int w  = threadIdx.x >> 5;    // head
    const int l  = threadIdx.x & 31;
    const int d0 = l * 2;

    const float* base = g_qkv + (size_t)bn * (3 * C_) + w * D_ + d0;
    float2 q = *(const float2*)(base);
    float2 k = *(const float2*)(base + C_);
    float2 v = *(const float2*)(base + 2 * C_);

    float sq = q.x * q.x + q.y * q.y;
    float sk = k.x * k.x + k.y * k.y;
#pragma unroll
    for (int ofs = 16; ofs >= 1; ofs >>= 1) {
        sq += __shfl_xor_sync(0xffffffffu, sq, ofs);
        sk += __shfl_xor_sync(0xffffffffu, sk, ofs);
    }
    const float rq = rsqrtf(sq * (1.f / 64.f) + 1e-6f);
    const float rk = rsqrtf(sk * (1.f / 64.f) + 1e-6f);

    float2 gq = *(const float2*)(qg + d0);
    float2 gk = *(const float2*)(kg + d0);
    const float qa = q.x * rq * gq.x, qb = q.y * rq * gq.y;
    const float ka = k.x * rk * gk.x, kb = k.y * rk * gk.y;

    float2 c = *(const float2*)(cosd + n * D_ + d0);
    float2 s = *(const float2*)(sind + n * D_ + d0);
    const float qo0 = qa * c.x - qb * s.x;
    const float qo1 = qb * c.y + qa * s.y;
    const float ko0 = ka * c.x - kb * s.x;
    const float ko1 = kb * c.y + ka * s.y;

    const int bh = b * H_ + w;
    const size_t qi = ((size_t)bh * D_ + d0) * N_ + n;
    g_q[qi]      = qo0;
    g_q[qi + N_] = qo1;
    g_k[qi]      = ko0;
    g_k[qi + N_] = ko1;
    *(float2*)&g_v[((size_t)bh * N_ + n) * D_ + d0] = v;
}

// =====================================================================
// Flash attention (fp32): Br=Bc=128, 256 threads.
// smem: Qt[64][128], Kt[64][128], Vs[128][64], Ps[128][128] = 160 KB.
// S micro-tile 8x8/thread (same mapping as SGEMM); softmax row stats via
// width-16 shfl (cols of a row live in one half-warp). Output written
// directly in (B,N,C) layout so the proj GEMM is a plain NT GEMM.
// =====================================================================
__global__ __launch_bounds__(256, 1)
void flash_kernel(float* __restrict__ out)
{
    extern __shared__ float sm[];
    float* Qt = sm;                   // [64][128]  (d-major, pre-scaled)
    float* Kt = sm + 64 * 128;        // [64][128]
    float* Vs = Kt + 64 * 128;        // [128][64]
    float* Ps = Vs + 128 * 64;        // [128][128]

    const int bh  = blockIdx.y;
    const int q0  = blockIdx.x * 128;
    const int tid = threadIdx.x;
    const int tx  = tid & 15;
    const int ty  = tid >> 4;

    const float* qg = g_q + (size_t)bh * D_ * N_;
    const float* kg = g_k + (size_t)bh * D_ * N_;
    const float* vg = g_v + (size_t)bh * N_ * D_;

    // Q tile, scaled by 1/sqrt(D) at load
    for (int idx = tid; idx < 64 * 32; idx += 256) {
        const int d = idx >> 5, c4 = idx & 31;
        float4 v4 = *(const float4*)&qg[(size_t)d * N_ + q0 + c4 * 4];
        v4.x *= 0.125f; v4.y *= 0.125f; v4.z *= 0.125f; v4.w *= 0.125f;
        *(float4*)&Qt[d * 128 + c4 * 4] = v4;
    }

    float o[8][4];
    float m_r[8], l_r[8];
#pragma unroll
    for (int i = 0; i < 8; i++) {
        m_r[i] = -1e30f; l_r[i] = 0.f;
#pragma unroll
        for (int j = 0; j < 4; j++) o[i][j] = 0.f;
    }

    for (int kt = 0; kt < N_ / 128; kt++) {
        const int kc0 = kt * 128;
        __syncthreads();   // prior PV finished reading Vs/Ps

        for (int idx = tid; idx < 2048; idx += 256) {
            const int d = idx >> 5, c4 = idx & 31;
            *(float4*)&Kt[d * 128 + c4 * 4] =
                *(const float4*)&kg[(size_t)d * N_ + kc0 + c4 * 4];
        }
        for (int idx = tid; idx < 2048; idx += 256) {
            const int c = idx >> 4, d4 = idx & 15;
            *(float4*)&Vs[c * 64 + d4 * 4] =
                *(const float4*)&vg[(size_t)(kc0 + c) * D_ + d4 * 4];
        }
        __syncthreads();

        // ---- S = (Q*scale) K^T ----
        float s[8][8];
#pragma unroll
        for (int i = 0; i < 8; i++)
#pragma unroll
            for (int j = 0; j < 8; j++) s[i][j] = 0.f;

#pragma unroll 8
        for (int d = 0; d < 64; d++) {
            float4 a0 = *(const float4*)&Qt[d * 128 + ty * 4];
            float4 a1 = *(const float4*)&Qt[d * 128 + 64 + ty * 4];
            float4 b0 = *(const float4*)&Kt[d * 128 + tx * 4];
            float4 b1 = *(const float4*)&Kt[d * 128 + 64 + tx * 4];
            float av[8] = {a0.x, a0.y, a0.z, a0.w, a1.x, a1.y, a1.z, a1.w};
            float bv[8] = {b0.x, b0.y, b0.z, b0.w, b1.x, b1.y, b1.z, b1.w};
#pragma unroll
            for (int i = 0; i < 8; i++)
#pragma unroll
                for (int j = 0; j < 8; j++)
                    s[i][j] = fmaf(av[i], bv[j], s[i][j]);
        }

        // ---- online softmax (rows of a tile live in one half-warp) ----
#pragma unroll
        for (int i = 0; i < 8; i++) {
            float mx = s[i][0];
#pragma unroll
            for (int j = 1; j < 8; j++) mx = fmaxf(mx, s[i][j]);
            mx = fmaxf(mx, __shfl_xor_sync(0xffffffffu, mx, 1));
            mx = fmaxf(mx, __shfl_xor_sync(0xffffffffu, mx, 2));
            mx = fmaxf(mx, __shfl_xor_sync(0xffffffffu, mx, 4));
            mx = fmaxf(mx, __shfl_xor_sync(0xffffffffu, mx, 8));
            const float mnew = fmaxf(m_r[i], mx);
            const float f = __expf(m_r[i] - mnew);
            m_r[i] = mnew;
            float rs = 0.f;
#pragma unroll
            for (int j = 0; j < 8; j++) {
                s[i][j] = __expf(s[i][j] - mnew);
                rs += s[i][j];
            }
            rs += __shfl_xor_sync(0xffffffffu, rs, 1);
            rs += __shfl_xor_sync(0xffffffffu, rs, 2);
            rs += __shfl_xor_sync(0xffffffffu, rs, 4);
            rs += __shfl_xor_sync(0xffffffffu, rs, 8);
            l_r[i] = l_r[i] * f + rs;
#pragma unroll
            for (int j = 0; j < 4; j++) o[i][j] *= f;
        }

        // stage P
#pragma unroll
        for (int i = 0; i < 8; i++) {
            const int r = (i < 4) ? (ty * 4 + i) : (64 + ty * 4 + i - 4);
            *(float4*)&Ps[r * 128 + tx * 4] =
                make_float4(s[i][0], s[i][1], s[i][2], s[i][3]);
            *(float4*)&Ps[r * 128 + 64 + tx * 4] =
                make_float4(s[i][4], s[i][5], s[i][6], s[i][7]);
        }
        __syncthreads();

        // ---- O += P V ----
        const int r0 = ty * 4;
#pragma unroll 4
        for (int c = 0; c < 128; c++) {
            const float4 v4 = *(const float4*)&Vs[c * 64 + tx * 4];
#pragma unroll
            for (int i = 0; i < 8; i++) {
                const int r = (i < 4) ? (r0 + i) : (64 + r0 + i - 4);
                const float p = Ps[r * 128 + c];
                o[i][0] = fmaf(p, v4.x, o[i][0]);
                o[i][1] = fmaf(p, v4.y, o[i][1]);
                o[i][2] = fmaf(p, v4.z, o[i][2]);
                o[i][3] = fmaf(p, v4.w, o[i][3]);
            }
        }
    }

    // epilogue: write (B,N,C) layout
    const int b = bh >> 4, h = bh & 15;
#pragma unroll
    for (int i = 0; i < 8; i++) {
        const int r = (i < 4) ? (ty * 4 + i) : (64 + ty * 4 + i - 4);
        const int n = q0 + r;
        const float inv = 1.f / l_r[i];
        float4 ov = make_float4(o[i][0] * inv, o[i][1] * inv,
                                o[i][2] * inv, o[i][3] * inv);
        *(float4*)&out[((size_t)(b * N_ + n)) * C_ + h * D_ + tx * 4] = ov;
    }
}

// =====================================================================
extern "C" void kernel_launch(void* const* d_in, const int* in_sizes, int n_in,
                              void* d_out, int out_size)
{
    const float* x      = (const float*)d_in[0];
    const float* cosd   = (const float*)d_in[1];
    const float* sind   = (const float*)d_in[2];
    const float* w_qkv  = (const float*)d_in[3];
    const float* w_proj = (const float*)d_in[4];
    const float* q_gam  = (const float*)d_in[5];
    const float* k_gam  = (const float*)d_in[6];
    float* out = (float*)d_out;

    float *p_qkv = nullptr, *p_att = nullptr;
    cudaGetSymbolAddress((void**)&p_qkv, g_qkv);
    cudaGetSymbolAddress((void**)&p_att, g_att);

    // 1) QKV projection: [8192,1024] x [3072,1024]^T
    sgemm_nt<<<dim3(3 * C_ / 128, BN_ / 128), 256>>>(x, w_qkv, p_qkv,
                                                     BN_, 3 * C_, C_);
    // 2) RMSNorm + RoPE + layout shuffle
    prep_kernel<<<BN_, 512>>>(cosd, sind, q_gam, k_gam);

    // 3) flash attention
    const int smem = (64 * 128 + 64 * 128 + 128 * 64 + 128 * 128) * 4; // 160 KB
    cudaFuncSetAttribute(flash_kernel,
                         cudaFuncAttributeMaxDynamicSharedMemorySize, smem);
    flash_kernel<<<dim3(N_ / 128, BH_), 256, smem>>>(p_att);

    // 4) output projection: [8192,1024] x [1024,1024]^T
    sgemm_nt<<<dim3(C_ / 128, BN_ / 128), 256>>>(p_att, w_proj, out,
                                                 BN_, C_, C_);
}

// round 3
// speedup vs baseline: 1.4512x; 1.4512x over previous
#include <cuda_runtime.h>
#include <cuda_bf16.h>
#include <cstdint>
#include <math.h>

#define B_  4
#define N_  2048
#define C_  1024
#define H_  16
#define D_  64
#define BH_ (B_ * H_)   // 64
#define BN_ (B_ * N_)   // 8192

// ---------------- scratch (device globals; no allocations allowed) ----------
__device__ float g_qkv[(size_t)BN_ * 3 * C_];            // [b*n][3C]
__device__ float g_q[(size_t)BH_ * D_ * N_];             // [bh][d][n]
__device__ float g_k[(size_t)BH_ * D_ * N_];             // [bh][d][n]
__device__ float g_v[(size_t)BH_ * N_ * D_];             // [bh][n][d]
__device__ __nv_bfloat16 g_xs[(size_t)2 * BN_ * C_];     // hi plane, lo plane
__device__ __nv_bfloat16 g_atts[(size_t)2 * BN_ * C_];
__device__ __nv_bfloat16 g_wqkvs[(size_t)2 * 3 * C_ * C_];
__device__ __nv_bfloat16 g_wprojs[(size_t)2 * C_ * C_];

// =====================================================================
// helpers (family-portable PTX only: cp.async / ldmatrix / mma.sync)
// =====================================================================
__device__ __forceinline__ uint32_t smem_u32(const void* p) {
    uint32_t a;
    asm("{ .reg .u64 t; cvta.to.shared.u64 t, %1; cvt.u32.u64 %0, t; }"
        : "=r"(a) : "l"(p));
    return a;
}

__device__ __forceinline__ void cpa16(uint32_t s, const void* g) {
    asm volatile("cp.async.cg.shared.global [%0], [%1], 16;"
                 :: "r"(s), "l"(g) : "memory");
}
#define CP_COMMIT()  asm volatile("cp.async.commit_group;" ::: "memory")
#define CP_WAIT(n)   asm volatile("cp.async.wait_group %0;" :: "n"(n) : "memory")

__device__ __forceinline__ void ldm4(uint32_t addr, uint32_t* r) {
    asm volatile("ldmatrix.sync.aligned.m8n8.x4.shared.b16 {%0,%1,%2,%3}, [%4];"
                 : "=r"(r[0]), "=r"(r[1]), "=r"(r[2]), "=r"(r[3]) : "r"(addr));
}

__device__ __forceinline__ void mma_bf16(float* c, const uint32_t* a, const uint32_t* b) {
    asm volatile(
        "mma.sync.aligned.m16n8k16.row.col.f32.bf16.bf16.f32 "
        "{%0,%1,%2,%3}, {%4,%5,%6,%7}, {%8,%9}, {%0,%1,%2,%3};"
        : "+f"(c[0]), "+f"(c[1]), "+f"(c[2]), "+f"(c[3])
        : "r"(a[0]), "r"(a[1]), "r"(a[2]), "r"(a[3]), "r"(b[0]), "r"(b[1]));
}

// =====================================================================
// fp32 -> (hi, lo) bf16 split. dst holds hi plane [0,n) then lo plane [n,2n).
// =====================================================================
__global__ void split_kernel(const float* __restrict__ src,
                             __nv_bfloat16* __restrict__ dst, size_t n)
{
    size_t i = ((size_t)blockIdx.x * blockDim.x + threadIdx.x) * 4;
    if (i >= n) return;
    float4 v = *(const float4*)(src + i);
    __nv_bfloat16 h0 = __float2bfloat16(v.x);
    __nv_bfloat16 h1 = __float2bfloat16(v.y);
    __nv_bfloat16 h2 = __float2bfloat16(v.z);
    __nv_bfloat16 h3 = __float2bfloat16(v.w);
    __nv_bfloat16 l0 = __float2bfloat16(v.x - __bfloat162float(h0));
    __nv_bfloat16 l1 = __float2bfloat16(v.y - __bfloat162float(h1));
    __nv_bfloat16 l2 = __float2bfloat16(v.z - __bfloat162float(h2));
    __nv_bfloat16 l3 = __float2bfloat16(v.w - __bfloat162float(h3));
    __nv_bfloat162* hp = (__nv_bfloat162*)(dst + i);
    hp[0] = __halves2bfloat162(h0, h1);
    hp[1] = __halves2bfloat162(h2, h3);
    __nv_bfloat162* lp = (__nv_bfloat162*)(dst + n + i);
    lp[0] = __halves2bfloat162(l0, l1);
    lp[1] = __halves2bfloat162(l2, l3);
}

// =====================================================================
// bf16x3 GEMM on mma.sync: C[M,N] = A[M,K]*B[N,K]^T  (~fp32 accuracy)
// A,B: bf16 [2][rows][K] planes (hi at 0, lo at +planeStride).
// CTA 128x128, BK=64, 256 thr (8 warps, warp tile 64x32), cp.async double buf.
// smem per stage: Ahi|Alo|Bhi|Blo each [128][64] bf16 (16KB) -> 64KB; x2 = 128KB
// =====================================================================
#define STG 65536
__global__ __launch_bounds__(256, 1)
void gemm_mma(const __nv_bfloat16* __restrict__ A, size_t planeA,
              const __nv_bfloat16* __restrict__ Bm, size_t planeB,
              float* __restrict__ C, int ldC, int K)
{
    extern __shared__ char smem[];
    const uint32_t sb = smem_u32(smem);
    const int tid  = threadIdx.x;
    const int lane = tid & 31;
    const int wid  = tid >> 5;
    const int m0 = blockIdx.y * 128;
    const int n0 = blockIdx.x * 128;
    const int wm = (wid >> 2) * 64;        // warp m offset in tile
    const int wn = (wid & 3) * 32;         // warp n offset in tile

    // ---- per-thread global load coords (4 chunks of 16B per array) ----
    int lrow[4], lc[4];
    uint32_t lsoff[4];
#pragma unroll
    for (int j = 0; j < 4; j++) {
        int idx = tid + 256 * j;           // 0..1023
        lrow[j] = idx >> 3;
        lc[j] = idx & 7;
        lsoff[j] = (uint32_t)(lrow[j] * 128 + ((lc[j] ^ (lrow[j] & 7)) << 4));
    }

    // ---- per-thread ldmatrix row offsets ----
    // A tiles: row = wm + mt*16 + (lane&15); chunk = kk*2 + (lane>>4)
    // B tiles: row = wn + nt*16 + ((lane>>4)<<3) + (lane&7); chunk = kk*2 + ((lane>>3)&1)
    uint32_t arow[4], brow[2];
#pragma unroll
    for (int mt = 0; mt < 4; mt++) arow[mt] = (uint32_t)((wm + mt * 16 + (lane & 15)) * 128);
#pragma unroll
    for (int nt = 0; nt < 2; nt++)
        brow[nt] = (uint32_t)((wn + nt * 16 + ((lane >> 4) << 3) + (lane & 7)) * 128);
    const int swz = lane & 7;
    const int cA = lane >> 4;              // 0/1
    const int cB = (lane >> 3) & 1;        // 0/1

    float acc[4][4][4];
#pragma unroll
    for (int i = 0; i < 4; i++)
#pragma unroll
        for (int j = 0; j < 4; j++)
#pragma unroll
            for (int r = 0; r < 4; r++) acc[i][j][r] = 0.f;

    const int KT = K >> 6;

    // ---- stage loader ----
    auto load_stage = [&](int buf, int kt) {
        const uint32_t st = sb + buf * STG;
        const int k0 = kt * 64;
#pragma unroll
        for (int j = 0; j < 4; j++) {
            const __nv_bfloat16* ga = A + (size_t)(m0 + lrow[j]) * K + k0 + lc[j] * 8;
            cpa16(st + lsoff[j], ga);
            cpa16(st + 16384 + lsoff[j], ga + planeA);
            const __nv_bfloat16* gb = Bm + (size_t)(n0 + lrow[j]) * K + k0 + lc[j] * 8;
            cpa16(st + 32768 + lsoff[j], gb);
            cpa16(st + 49152 + lsoff[j], gb + planeB);
        }
        CP_COMMIT();
    };

    load_stage(0, 0);

    int buf = 0;
#pragma unroll 1
    for (int kt = 0; kt < KT; kt++) {
        if (kt + 1 < KT) { load_stage(buf ^ 1, kt + 1); CP_WAIT(1); }
        else             { CP_WAIT(0); }
        __syncthreads();

        const uint32_t st = sb + buf * STG;
#pragma unroll
        for (int kk = 0; kk < 4; kk++) {
            uint32_t ah[4][4], al[4][4], bh[2][4], bl[2][4];
            const uint32_t swA = (uint32_t)(((kk * 2 + cA) ^ swz) << 4);
            const uint32_t swB = (uint32_t)(((kk * 2 + cB) ^ swz) << 4);
#pragma unroll
            for (int mt = 0; mt < 4; mt++) {
                ldm4(st + arow[mt] + swA, ah[mt]);
                ldm4(st + 16384 + arow[mt] + swA, al[mt]);
            }
#pragma unroll
            for (int nt = 0; nt < 2; nt++) {
                ldm4(st + 32768 + brow[nt] + swB, bh[nt]);
                ldm4(st + 49152 + brow[nt] + swB, bl[nt]);
            }
#pragma unroll
            for (int mt = 0; mt < 4; mt++)
#pragma unroll
                for (int nt = 0; nt < 2; nt++)
#pragma unroll
                    for (int h = 0; h < 2; h++) {
                        const int ng = nt * 2 + h;
                        mma_bf16(acc[mt][ng], ah[mt], &bh[nt][h * 2]);
                        mma_bf16(acc[mt][ng], ah[mt], &bl[nt][h * 2]);
                        mma_bf16(acc[mt][ng], al[mt], &bh[nt][h * 2]);
                    }
        }
        __syncthreads();
        buf ^= 1;
    }

    // ---- epilogue ----
    const int g = lane >> 2, tg = lane & 3;
#pragma unroll
    for (int mt = 0; mt < 4; mt++)
#pragma unroll
        for (int ng = 0; ng < 4; ng++) {
            const int row = m0 + wm + mt * 16 + g;
            const int col = n0 + wn + ng * 8 + tg * 2;
            *(float2*)&C[(size_t)row * ldC + col] =
                make_float2(acc[mt][ng][0], acc[mt][ng][1]);
            *(float2*)&C[(size_t)(row + 8) * ldC + col] =
                make_float2(acc[mt][ng][2], acc[mt][ng][3]);
        }
}

// =====================================================================
// Prep: per (b,n,h) RMSNorm (fp32) + interleaved RoPE on q,k; copy v.
// =====================================================================
__global__ void prep_kernel(const float* __restrict__ cosd,
                            const float* __restrict__ sind,
                            const float* __restrict__ qg,
                            const float* __restrict__ kg)
{
    const int bn = blockIdx.x;
    const int n  = bn & (N_ - 1);
    const int b  = bn >> 11;
    const int w  = threadIdx.x >> 5;
    const int l  = threadIdx.x & 31;
    const int d0 = l * 2;

    const float* base = g_qkv + (size_t)bn * (3 * C_) + w * D_ + d0;
    float2 q = *(const float2*)(base);
    float2 k = *(const float2*)(base + C_);
    float2 v = *(const float2*)(base + 2 * C_);

    float sq = q.x * q.x + q.y * q.y;
    float sk = k.x * k.x + k.y * k.y;
#pragma unroll
    for (int ofs = 16; ofs >= 1; ofs >>= 1) {
        sq += __shfl_xor_sync(0xffffffffu, sq, ofs);
        sk += __shfl_xor_sync(0xffffffffu, sk, ofs);
    }
    const float rq = rsqrtf(sq * (1.f / 64.f) + 1e-6f);
    const float rk = rsqrtf(sk * (1.f / 64.f) + 1e-6f);

    float2 gq = *(const float2*)(qg + d0);
    float2 gk = *(const float2*)(kg + d0);
    const float qa = q.x * rq * gq.x, qb = q.y * rq * gq.y;
    const float ka = k.x * rk * gk.x, kb = k.y * rk * gk.y;

    float2 c = *(const float2*)(cosd + n * D_ + d0);
    float2 s = *(const float2*)(sind + n * D_ + d0);
    const float qo0 = qa * c.x - qb * s.x;
    const float qo1 = qb * c.y + qa * s.y;
    const float ko0 = ka * c.x - kb * s.x;
    const float ko1 = kb * c.y + ka * s.y;

    const int bh = b * H_ + w;
    const size_t qi = ((size_t)bh * D_ + d0) * N_ + n;
    g_q[qi]      = qo0;
    g_q[qi + N_] = qo1;
    g_k[qi]      = ko0;
    g_k[qi + N_] = ko1;
    *(float2*)&g_v[((size_t)bh * N_ + n) * D_ + d0] = v;
}

// =====================================================================
// Flash attention (fp32 SIMT): Br=Bc=128, 256 threads.
// Epilogue now writes bf16 (hi,lo) planes directly (fuses the att split).
// =====================================================================
__global__ __launch_bounds__(256, 1)
void flash_kernel(__nv_bfloat16* __restrict__ outs)
{
    extern __shared__ float sm[];
    float* Qt = sm;
    float* Kt = sm + 64 * 128;
    float* Vs = Kt + 64 * 128;
    float* Ps = Vs + 128 * 64;

    const int bh  = blockIdx.y;
    const int q0  = blockIdx.x * 128;
    const int tid = threadIdx.x;
    const int tx  = tid & 15;
    const int ty  = tid >> 4;

    const float* qg = g_q + (size_t)bh * D_ * N_;
    const float* kg = g_k + (size_t)bh * D_ * N_;
    const float* vg = g_v + (size_t)bh * N_ * D_;

    for (int idx = tid; idx < 64 * 32; idx += 256) {
        const int d = idx >> 5, c4 = idx & 31;
        float4 v4 = *(const float4*)&qg[(size_t)d * N_ + q0 + c4 * 4];
        v4.x *= 0.125f; v4.y *= 0.125f; v4.z *= 0.125f; v4.w *= 0.125f;
        *(float4*)&Qt[d * 128 + c4 * 4] = v4;
    }

    float o[8][4];
    float m_r[8], l_r[8];
#pragma unroll
    for (int i = 0; i < 8; i++) {
        m_r[i] = -1e30f; l_r[i] = 0.f;
#pragma unroll
        for (int j = 0; j < 4; j++) o[i][j] = 0.f;
    }

    for (int kt = 0; kt < N_ / 128; kt++) {
        const int kc0 = kt * 128;
        __syncthreads();

        for (int idx = tid; idx < 2048; idx += 256) {
            const int d = idx >> 5, c4 = idx & 31;
            *(float4*)&Kt[d * 128 + c4 * 4] =
                *(const float4*)&kg[(size_t)d * N_ + kc0 + c4 * 4];
        }
        for (int idx = tid; idx < 2048; idx += 256) {
            const int c = idx >> 4, d4 = idx & 15;
            *(float4*)&Vs[c * 64 + d4 * 4] =
                *(const float4*)&vg[(size_t)(kc0 + c) * D_ + d4 * 4];
        }
        __syncthreads();

        float s[8][8];
#pragma unroll
        for (int i = 0; i < 8; i++)
#pragma unroll
            for (int j = 0; j < 8; j++) s[i][j] = 0.f;

#pragma unroll 8
        for (int d = 0; d < 64; d++) {
            float4 a0 = *(const float4*)&Qt[d * 128 + ty * 4];
            float4 a1 = *(const float4*)&Qt[d * 128 + 64 + ty * 4];
            float4 b0 = *(const float4*)&Kt[d * 128 + tx * 4];
            float4 b1 = *(const float4*)&Kt[d * 128 + 64 + tx * 4];
            float av[8] = {a0.x, a0.y, a0.z, a0.w, a1.x, a1.y, a1.z, a1.w};
            float bv[8] = {b0.x, b0.y, b0.z, b0.w, b1.x, b1.y, b1.z, b1.w};
#pragma unroll
            for (int i = 0; i < 8; i++)
#pragma unroll
                for (int j = 0; j < 8; j++)
                    s[i][j] = fmaf(av[i], bv[j], s[i][j]);
        }

#pragma unroll
        for (int i = 0; i < 8; i++) {
            float mx = s[i][0];
#pragma unroll
            for (int j = 1; j < 8; j++) mx = fmaxf(mx, s[i][j]);
            mx = fmaxf(mx, __shfl_xor_sync(0xffffffffu, mx, 1));
            mx = fmaxf(mx, __shfl_xor_sync(0xffffffffu, mx, 2));
            mx = fmaxf(mx, __shfl_xor_sync(0xffffffffu, mx, 4));
            mx = fmaxf(mx, __shfl_xor_sync(0xffffffffu, mx, 8));
            const float mnew = fmaxf(m_r[i], mx);
            const float f = __expf(m_r[i] - mnew);
            m_r[i] = mnew;
            float rs = 0.f;
#pragma unroll
            for (int j = 0; j < 8; j++) {
                s[i][j] = __expf(s[i][j] - mnew);
                rs += s[i][j];
            }
            rs += __shfl_xor_sync(0xffffffffu, rs, 1);
            rs += __shfl_xor_sync(0xffffffffu, rs, 2);
            rs += __shfl_xor_sync(0xffffffffu, rs, 4);
            rs += __shfl_xor_sync(0xffffffffu, rs, 8);
            l_r[i] = l_r[i] * f + rs;
#pragma unroll
            for (int j = 0; j < 4; j++) o[i][j] *= f;
        }

#pragma unroll
        for (int i = 0; i < 8; i++) {
            const int r = (i < 4) ? (ty * 4 + i) : (64 + ty * 4 + i - 4);
            *(float4*)&Ps[r * 128 + tx * 4] =
                make_float4(s[i][0], s[i][1], s[i][2], s[i][3]);
            *(float4*)&Ps[r * 128 + 64 + tx * 4] =
                make_float4(s[i][4], s[i][5], s[i][6], s[i][7]);
        }
        __syncthreads();

        const int r0 = ty * 4;
#pragma unroll 4
        for (int c = 0; c < 128; c++) {
            const float4 v4 = *(const float4*)&Vs[c * 64 + tx * 4];
#pragma unroll
            for (int i = 0; i < 8; i++) {
                const int r = (i < 4) ? (r0 + i) : (64 + r0 + i - 4);
                const float p = Ps[r * 128 + c];
                o[i][0] = fmaf(p, v4.x, o[i][0]);
                o[i][1] = fmaf(p, v4.y, o[i][1]);
                o[i][2] = fmaf(p, v4.z, o[i][2]);
                o[i][3] = fmaf(p, v4.w, o[i][3]);
            }
        }
    }

    // epilogue: write bf16 hi/lo planes (fused split)
    const size_t nx = (size_t)BN_ * C_;
    const int b = bh >> 4, h = bh & 15;
#pragma unroll
    for (int i = 0; i < 8; i++) {
        const int r = (i < 4) ? (ty * 4 + i) : (64 + ty * 4 + i - 4);
        const int n = q0 + r;
        const float inv = 1.f / l_r[i];
        float v0 = o[i][0] * inv, v1 = o[i][1] * inv;
        float v2 = o[i][2] * inv, v3 = o[i][3] * inv;
        __nv_bfloat16 h0 = __float2bfloat16(v0);
        __nv_bfloat16 h1 = __float2bfloat16(v1);
        __nv_bfloat16 h2 = __float2bfloat16(v2);
        __nv_bfloat16 h3 = __float2bfloat16(v3);
        const size_t oi = ((size_t)(b * N_ + n)) * C_ + h * D_ + tx * 4;
        __nv_bfloat162* hp = (__nv_bfloat162*)(outs + oi);
        hp[0] = __halves2bfloat162(h0, h1);
        hp[1] = __halves2bfloat162(h2, h3);
        __nv_bfloat162* lp = (__nv_bfloat162*)(outs + nx + oi);
        lp[0] = __halves2bfloat162(__float2bfloat16(v0 - __bfloat162float(h0)),
                                   __float2bfloat16(v1 - __bfloat162float(h1)));
        lp[1] = __halves2bfloat162(__float2bfloat16(v2 - __bfloat162float(h2)),
                                   __float2bfloat16(v3 - __bfloat162float(h3)));
    }
}

// =====================================================================
extern "C" void kernel_launch(void* const* d_in, const int* in_sizes, int n_in,
                              void* d_out, int out_size)
{
    const float* x      = (const float*)d_in[0];
    const float* cosd   = (const float*)d_in[1];
    const float* sind   = (const float*)d_in[2];
    const float* w_qkv  = (const float*)d_in[3];
    const float* w_proj = (const float*)d_in[4];
    const float* q_gam  = (const float*)d_in[5];
    const float* k_gam  = (const float*)d_in[6];
    float* out = (float*)d_out;

    float* p_qkv = nullptr;
    __nv_bfloat16 *p_xs = nullptr, *p_atts = nullptr, *p_wqkvs = nullptr, *p_wprojs = nullptr;
    cudaGetSymbolAddress((void**)&p_qkv, g_qkv);
    cudaGetSymbolAddress((void**)&p_xs, g_xs);
    cudaGetSymbolAddress((void**)&p_atts, g_atts);
    cudaGetSymbolAddress((void**)&p_wqkvs, g_wqkvs);
    cudaGetSymbolAddress((void**)&p_wprojs, g_wprojs);

    const size_t n_x = (size_t)BN_ * C_;
    const size_t n_wqkv = (size_t)3 * C_ * C_;
    const size_t n_wproj = (size_t)C_ * C_;

    cudaFuncSetAttribute(gemm_mma,
                         cudaFuncAttributeMaxDynamicSharedMemorySize, 2 * STG);

    // 1) split inputs to (hi,lo) bf16 planes
    split_kernel<<<(int)(n_x / 4 / 256), 256>>>(x, p_xs, n_x);
    split_kernel<<<(int)(n_wqkv / 4 / 256), 256>>>(w_qkv, p_wqkvs, n_wqkv);
    split_kernel<<<(int)(n_wproj / 4 / 256), 256>>>(w_proj, p_wprojs, n_wproj);

    // 2) QKV projection (tensor cores, bf16x3): [8192,1024] x [3072,1024]^T
    gemm_mma<<<dim3(3 * C_ / 128, BN_ / 128), 256, 2 * STG>>>(
        p_xs, n_x, p_wqkvs, n_wqkv, p_qkv, 3 * C_, C_);

    // 3) RMSNorm + RoPE + layout shuffle
    prep_kernel<<<BN_, 512>>>(cosd, sind, q_gam, k_gam);

    // 4) flash attention (fp32 SIMT), epilogue emits bf16 hi/lo planes
    const int smem = (64 * 128 + 64 * 128 + 128 * 64 + 128 * 128) * 4; // 160 KB
    cudaFuncSetAttribute(flash_kernel,
                         cudaFuncAttributeMaxDynamicSharedMemorySize, smem);
    flash_kernel<<<dim3(N_ / 128, BH_), 256, smem>>>(p_atts);

    // 5) output projection (tensor cores, bf16x3): [8192,1024] x [1024,1024]^T
    gemm_mma<<<dim3(C_ / 128, BN_ / 128), 256, 2 * STG>>>(
        p_atts, n_x, p_wprojs, n_wproj, out, C_, C_);
}

// round 4
// speedup vs baseline: 2.1064x; 1.4515x over previous
#include <cuda_runtime.h>
#include <cuda_bf16.h>
#include <cstdint>
#include <math.h>

#define B_  4
#define N_  2048
#define C_  1024
#define H_  16
#define D_  64
#define BH_ (B_ * H_)   // 64
#define BN_ (B_ * N_)   // 8192

// ---------------- scratch (device globals; no allocations allowed) ----------
__device__ float g_qkv[(size_t)BN_ * 3 * C_];            // [b*n][3C]
__device__ __nv_bfloat16 g_xs[(size_t)2 * BN_ * C_];     // hi plane, lo plane
__device__ __nv_bfloat16 g_atts[(size_t)2 * BN_ * C_];
__device__ __nv_bfloat16 g_wqkvs[(size_t)2 * 3 * C_ * C_];
__device__ __nv_bfloat16 g_wprojs[(size_t)2 * C_ * C_];
__device__ __nv_bfloat16 g_qb[(size_t)2 * BH_ * N_ * D_];  // [2][bh][n][d], pre-scaled
__device__ __nv_bfloat16 g_kb[(size_t)2 * BH_ * N_ * D_];  // [2][bh][n][d]
__device__ __nv_bfloat16 g_vb[(size_t)2 * BH_ * D_ * N_];  // [2][bh][d][n]

#define QKP ((size_t)BH_ * N_ * D_)   // plane stride for q/k/v bf16 buffers

// =====================================================================
// helpers (family-portable PTX only: cp.async / ldmatrix / mma.sync)
// =====================================================================
__device__ __forceinline__ uint32_t smem_u32(const void* p) {
    uint32_t a;
    asm("{ .reg .u64 t; cvta.to.shared.u64 t, %1; cvt.u32.u64 %0, t; }"
        : "=r"(a) : "l"(p));
    return a;
}

__device__ __forceinline__ void cpa16(uint32_t s, const void* g) {
    asm volatile("cp.async.cg.shared.global [%0], [%1], 16;"
                 :: "r"(s), "l"(g) : "memory");
}
#define CP_COMMIT()  asm volatile("cp.async.commit_group;" ::: "memory")
#define CP_WAIT(n)   asm volatile("cp.async.wait_group %0;" :: "n"(n) : "memory")

__device__ __forceinline__ void ldm4(uint32_t addr, uint32_t* r) {
    asm volatile("ldmatrix.sync.aligned.m8n8.x4.shared.b16 {%0,%1,%2,%3}, [%4];"
                 : "=r"(r[0]), "=r"(r[1]), "=r"(r[2]), "=r"(r[3]) : "r"(addr));
}

__device__ __forceinline__ void mma_bf16(float* c, const uint32_t* a, const uint32_t* b) {
    asm volatile(
        "mma.sync.aligned.m16n8k16.row.col.f32.bf16.bf16.f32 "
        "{%0,%1,%2,%3}, {%4,%5,%6,%7}, {%8,%9}, {%0,%1,%2,%3};"
        : "+f"(c[0]), "+f"(c[1]), "+f"(c[2]), "+f"(c[3])
        : "r"(a[0]), "r"(a[1]), "r"(a[2]), "r"(a[3]), "r"(b[0]), "r"(b[1]));
}

__device__ __forceinline__ uint32_t pack_bf2(float a, float b) {
    __nv_bfloat162 t = __floats2bfloat162_rn(a, b);
    return *(uint32_t*)&t;
}

// =====================================================================
// fp32 -> (hi, lo) bf16 split planes
// =====================================================================
__global__ void split_kernel(const float* __restrict__ src,
                             __nv_bfloat16* __restrict__ dst, size_t n)
{
    size_t i = ((size_t)blockIdx.x * blockDim.x + threadIdx.x) * 4;
    if (i >= n) return;
    float4 v = *(const float4*)(src + i);
    __nv_bfloat16 h0 = __float2bfloat16(v.x);
    __nv_bfloat16 h1 = __float2bfloat16(v.y);
    __nv_bfloat16 h2 = __float2bfloat16(v.z);
    __nv_bfloat16 h3 = __float2bfloat16(v.w);
    __nv_bfloat162* hp = (__nv_bfloat162*)(dst + i);
    hp[0] = __halves2bfloat162(h0, h1);
    hp[1] = __halves2bfloat162(h2, h3);
    __nv_bfloat162* lp = (__nv_bfloat162*)(dst + n + i);
    lp[0] = __halves2bfloat162(__float2bfloat16(v.x - __bfloat162float(h0)),
                               __float2bfloat16(v.y - __bfloat162float(h1)));
    lp[1] = __halves2bfloat162(__float2bfloat16(v.z - __bfloat162float(h2)),
                               __float2bfloat16(v.w - __bfloat162float(h3)));
}

// =====================================================================
// bf16x3 GEMM on mma.sync (validated in R3): C = A[M,K]*B[N,K]^T
// =====================================================================
#define STG 65536
__global__ __launch_bounds__(256, 1)
void gemm_mma(const __nv_bfloat16* __restrict__ A, size_t planeA,
              const __nv_bfloat16* __restrict__ Bm, size_t planeB,
              float* __restrict__ C, int ldC, int K)
{
    extern __shared__ char smem[];
    const uint32_t sb = smem_u32(smem);
    const int tid  = threadIdx.x;
    const int lane = tid & 31;
    const int wid  = tid >> 5;
    const int m0 = blockIdx.y * 128;
    const int n0 = blockIdx.x * 128;
    const int wm = (wid >> 2) * 64;
    const int wn = (wid & 3) * 32;

    int lrow[4], lc[4];
    uint32_t lsoff[4];
#pragma unroll
    for (int j = 0; j < 4; j++) {
        int idx = tid + 256 * j;
        lrow[j] = idx >> 3;
        lc[j] = idx & 7;
        lsoff[j] = (uint32_t)(lrow[j] * 128 + ((lc[j] ^ (lrow[j] & 7)) << 4));
    }

    uint32_t arow[4], brow[2];
#pragma unroll
    for (int mt = 0; mt < 4; mt++) arow[mt] = (uint32_t)((wm + mt * 16 + (lane & 15)) * 128);
#pragma unroll
    for (int nt = 0; nt < 2; nt++)
        brow[nt] = (uint32_t)((wn + nt * 16 + ((lane >> 4) << 3) + (lane & 7)) * 128);
    const int swz = lane & 7;
    const int cA = lane >> 4;
    const int cB = (lane >> 3) & 1;

    float acc[4][4][4];
#pragma unroll
    for (int i = 0; i < 4; i++)
#pragma unroll
        for (int j = 0; j < 4; j++)
#pragma unroll
            for (int r = 0; r < 4; r++) acc[i][j][r] = 0.f;

    const int KT = K >> 6;

    auto load_stage = [&](int buf, int kt) {
        const uint32_t st = sb + buf * STG;
        const int k0 = kt * 64;
#pragma unroll
        for (int j = 0; j < 4; j++) {
            const __nv_bfloat16* ga = A + (size_t)(m0 + lrow[j]) * K + k0 + lc[j] * 8;
            cpa16(st + lsoff[j], ga);
            cpa16(st + 16384 + lsoff[j], ga + planeA);
            const __nv_bfloat16* gb = Bm + (size_t)(n0 + lrow[j]) * K + k0 + lc[j] * 8;
            cpa16(st + 32768 + lsoff[j], gb);
            cpa16(st + 49152 + lsoff[j], gb + planeB);
        }
        CP_COMMIT();
    };

    load_stage(0, 0);

    int buf = 0;
#pragma unroll 1
    for (int kt = 0; kt < KT; kt++) {
        if (kt + 1 < KT) { load_stage(buf ^ 1, kt + 1); CP_WAIT(1); }
        else             { CP_WAIT(0); }
        __syncthreads();

        const uint32_t st = sb + buf * STG;
#pragma unroll
        for (int kk = 0; kk < 4; kk++) {
            uint32_t ah[4][4], al[4][4], bh[2][4], bl[2][4];
            const uint32_t swA = (uint32_t)(((kk * 2 + cA) ^ swz) << 4);
            const uint32_t swB = (uint32_t)(((kk * 2 + cB) ^ swz) << 4);
#pragma unroll
            for (int mt = 0; mt < 4; mt++) {
                ldm4(st + arow[mt] + swA, ah[mt]);
                ldm4(st + 16384 + arow[mt] + swA, al[mt]);
            }
#pragma unroll
            for (int nt = 0; nt < 2; nt++) {
                ldm4(st + 32768 + brow[nt] + swB, bh[nt]);
                ldm4(st + 49152 + brow[nt] + swB, bl[nt]);
            }
#pragma unroll
            for (int mt = 0; mt < 4; mt++)
#pragma unroll
                for (int nt = 0; nt < 2; nt++)
#pragma unroll
                    for (int h = 0; h < 2; h++) {
                        const int ng = nt * 2 + h;
                        mma_bf16(acc[mt][ng], ah[mt], &bh[nt][h * 2]);
                        mma_bf16(acc[mt][ng], ah[mt], &bl[nt][h * 2]);
                        mma_bf16(acc[mt][ng], al[mt], &bh[nt][h * 2]);
                    }
        }
        __syncthreads();
        buf ^= 1;
    }

    const int g = lane >> 2, tg = lane & 3;
#pragma unroll
    for (int mt = 0; mt < 4; mt++)
#pragma unroll
        for (int ng = 0; ng < 4; ng++) {
            const int row = m0 + wm + mt * 16 + g;
            const int col = n0 + wn + ng * 8 + tg * 2;
            *(float2*)&C[(size_t)row * ldC + col] =
                make_float2(acc[mt][ng][0], acc[mt][ng][1]);
            *(float2*)&C[(size_t)(row + 8) * ldC + col] =
                make_float2(acc[mt][ng][2], acc[mt][ng][3]);
        }
}

// =====================================================================
// Prep: RMSNorm + RoPE on q,k -> bf16 hi/lo planes [bh][n][d], q pre-scaled.
// =====================================================================
__global__ void prep_kernel(const float* __restrict__ cosd,
                            const float* __restrict__ sind,
                            const float* __restrict__ qg,
                            const float* __restrict__ kg)
{
    const int bn = blockIdx.x;
    const int n  = bn & (N_ - 1);
    const int b  = bn >> 11;
    const int w  = threadIdx.x >> 5;
    const int l  = threadIdx.x & 31;
    const int d0 = l * 2;

    const float* base = g_qkv + (size_t)bn * (3 * C_) + w * D_ + d0;
    float2 q = *(const float2*)(base);
    float2 k = *(const float2*)(base + C_);

    float sq = q.x * q.x + q.y * q.y;
    float sk = k.x * k.x + k.y * k.y;
#pragma unroll
    for (int ofs = 16; ofs >= 1; ofs >>= 1) {
        sq += __shfl_xor_sync(0xffffffffu, sq, ofs);
        sk += __shfl_xor_sync(0xffffffffu, sk, ofs);
    }
    const float rq = rsqrtf(sq * (1.f / 64.f) + 1e-6f);
    const float rk = rsqrtf(sk * (1.f / 64.f) + 1e-6f);

    float2 gq = *(const float2*)(qg + d0);
    float2 gk = *(const float2*)(kg + d0);
    const float qa = q.x * rq * gq.x, qb = q.y * rq * gq.y;
    const float ka = k.x * rk * gk.x, kb = k.y * rk * gk.y;

    float2 c = *(const float2*)(cosd + n * D_ + d0);
    float2 s = *(const float2*)(sind + n * D_ + d0);
    const float qo0 = (qa * c.x - qb * s.x) * 0.125f;   // fold 1/sqrt(D)
    const float qo1 = (qb * c.y + qa * s.y) * 0.125f;
    const float ko0 = ka * c.x - kb * s.x;
    const float ko1 = kb * c.y + ka * s.y;

    const int bh = b * H_ + w;
    const size_t qi = ((size_t)bh * N_ + n) * D_ + d0;

    __nv_bfloat16 qh0 = __float2bfloat16(qo0), qh1 = __float2bfloat16(qo1);
    *(__nv_bfloat162*)&g_qb[qi] = __halves2bfloat162(qh0, qh1);
    *(__nv_bfloat162*)&g_qb[QKP + qi] =
        __halves2bfloat162(__float2bfloat16(qo0 - __bfloat162float(qh0)),
                           __float2bfloat16(qo1 - __bfloat162float(qh1)));
    __nv_bfloat16 kh0 = __float2bfloat16(ko0), kh1 = __float2bfloat16(ko1);
    *(__nv_bfloat162*)&g_kb[qi] = __halves2bfloat162(kh0, kh1);
    *(__nv_bfloat162*)&g_kb[QKP + qi] =
        __halves2bfloat162(__float2bfloat16(ko0 - __bfloat162float(kh0)),
                           __float2bfloat16(ko1 - __bfloat162float(kh1)));
}

// =====================================================================
// V transpose: g_qkv v-part [b][n][h*64+d] -> g_vb [2][bh][d][n] bf16 hi/lo
// =====================================================================
__global__ void vtrans_kernel()
{
    __shared__ float t[64][65];
    const int bh = blockIdx.x;
    const int n0 = blockIdx.y * 64;
    const int b = bh >> 4, h = bh & 15;
    const int tid = threadIdx.x;

    for (int i = tid; i < 4096; i += 256) {
        const int r = i >> 6, c = i & 63;
        t[c][r] = g_qkv[((size_t)(b * N_ + n0 + r)) * (3 * C_) + 2 * C_ + h * 64 + c];
    }
    __syncthreads();
    for (int i = tid; i < 4096; i += 256) {
        const int d = i >> 6, n = i & 63;
        const float v = t[d][n];
        const __nv_bfloat16 hv = __float2bfloat16(v);
        const size_t oi = ((size_t)bh * D_ + d) * N_ + n0 + n;
        g_vb[oi] = hv;
        g_vb[QKP + oi] = __float2bfloat16(v - __bfloat162float(hv));
    }
}

// =====================================================================
// Flash attention on tensor cores (bf16x3).
// CTA: 128 q-rows x one bh; 8 warps, warp owns 16 rows (full 128-col stripe).
// smem: Qhi|Qlo [128][64] resident (32 KB) + 2 stages of Khi|Klo|Vhi|Vlo
// (64 KB each) = 160 KB. cp.async double-buffered K/V.
// =====================================================================
#define FSTG 65536
#define FLASH_SMEM (32768 + 2 * FSTG)

__global__ __launch_bounds__(256, 1)
void flash_mma(__nv_bfloat16* __restrict__ outs)
{
    extern __shared__ char smem[];
    const uint32_t sb = smem_u32(smem);
    const int bh  = blockIdx.y;
    const int q0  = blockIdx.x * 128;
    const int tid = threadIdx.x;
    const int lane = tid & 31;
    const int wid  = tid >> 5;

    const __nv_bfloat16* qbp = g_qb + (size_t)bh * N_ * D_;
    const __nv_bfloat16* kbp = g_kb + (size_t)bh * N_ * D_;
    const __nv_bfloat16* vbp = g_vb + (size_t)bh * D_ * N_;

    // global->smem load pattern (1024 16B chunks per 16KB plane)
    int lrow[4], lc[4];
    uint32_t lsoff[4];
#pragma unroll
    for (int j = 0; j < 4; j++) {
        int idx = tid + 256 * j;
        lrow[j] = idx >> 3;
        lc[j] = idx & 7;
        lsoff[j] = (uint32_t)(lrow[j] * 128 + ((lc[j] ^ (lrow[j] & 7)) << 4));
    }

    // Q tile (resident): hi at 0, lo at 16384
#pragma unroll
    for (int j = 0; j < 4; j++) {
        const __nv_bfloat16* gq = qbp + (size_t)(q0 + lrow[j]) * D_ + lc[j] * 8;
        cpa16(sb + lsoff[j], gq);
        cpa16(sb + 16384 + lsoff[j], gq + QKP);
    }

    auto load_stage = [&](int buf, int kt) {
        const uint32_t st = sb + 32768 + buf * FSTG;
        const int kc0 = kt * 128;
#pragma unroll
        for (int j = 0; j < 4; j++) {
            const __nv_bfloat16* gk = kbp + (size_t)(kc0 + lrow[j]) * D_ + lc[j] * 8;
            cpa16(st + lsoff[j], gk);                 // Khi
            cpa16(st + 16384 + lsoff[j], gk + QKP);   // Klo
            // V smem row r = blk*64 + d ; global [d][kc0 + blk*64 + ...]
            const int blk = lrow[j] >> 6, d = lrow[j] & 63;
            const __nv_bfloat16* gv = vbp + (size_t)d * N_ + kc0 + blk * 64 + lc[j] * 8;
            cpa16(st + 32768 + lsoff[j], gv);         // Vhi
            cpa16(st + 49152 + lsoff[j], gv + QKP);   // Vlo
        }
        CP_COMMIT();
    };

    load_stage(0, 0);   // group with Q loads
    load_stage(1, 1);

    // ldmatrix offsets
    const int swz = lane & 7;
    const int cA = lane >> 4;
    const int cB = (lane >> 3) & 1;
    const uint32_t aoff = (uint32_t)((wid * 16 + (lane & 15)) * 128);
    uint32_t boff[8];
#pragma unroll
    for (int nt = 0; nt < 8; nt++)
        boff[nt] = (uint32_t)((nt * 16 + ((lane >> 4) << 3) + (lane & 7)) * 128);

    float oc[8][4];
    float m_r[2], l_r[2];
#pragma unroll
    for (int i = 0; i < 8; i++)
#pragma unroll
        for (int j = 0; j < 4; j++) oc[i][j] = 0.f;
    m_r[0] = m_r[1] = -1e30f;
    l_r[0] = l_r[1] = 0.f;

#pragma unroll 1
    for (int kt = 0; kt < N_ / 128; kt++) {
        CP_WAIT(1);
        __syncthreads();
        const uint32_t st = sb + 32768 + (kt & 1) * FSTG;

        // ---- S = Q K^T (3-pass bf16x3) ----
        float sc[16][4];
#pragma unroll
        for (int i = 0; i < 16; i++)
#pragma unroll
            for (int j = 0; j < 4; j++) sc[i][j] = 0.f;

#pragma unroll
        for (int kk = 0; kk < 4; kk++) {
            const uint32_t swA = (uint32_t)(((kk * 2 + cA) ^ swz) << 4);
            const uint32_t swB = (uint32_t)(((kk * 2 + cB) ^ swz) << 4);
            uint32_t aq[4], aql[4];
            ldm4(sb + aoff + swA, aq);
            ldm4(sb + 16384 + aoff + swA, aql);
#pragma unroll
            for (int nt = 0; nt < 8; nt++) {
                uint32_t kh[4], kl[4];
                ldm4(st + boff[nt] + swB, kh);
                ldm4(st + 16384 + boff[nt] + swB, kl);
#pragma unroll
                for (int h = 0; h < 2; h++) {
                    const int ng = nt * 2 + h;
                    mma_bf16(sc[ng], aq, &kh[h * 2]);
                    mma_bf16(sc[ng], aq, &kl[h * 2]);
                    mma_bf16(sc[ng], aql, &kh[h * 2]);
                }
            }
        }

        // ---- online softmax (rows r=lane>>2 and r+8; stats via 2 shfls) ----
#pragma unroll
        for (int p = 0; p < 2; p++) {
            float mx = -1e30f;
#pragma unroll
            for (int ng = 0; ng < 16; ng++)
                mx = fmaxf(mx, fmaxf(sc[ng][2 * p], sc[ng][2 * p + 1]));
            mx = fmaxf(mx, __shfl_xor_sync(0xffffffffu, mx, 1));
            mx = fmaxf(mx, __shfl_xor_sync(0xffffffffu, mx, 2));
            const float mnew = fmaxf(m_r[p], mx);
            const float f = __expf(m_r[p] - mnew);
            m_r[p] = mnew;
            float rs = 0.f;
#pragma unroll
            for (int ng = 0; ng < 16; ng++) {
                sc[ng][2 * p]     = __expf(sc[ng][2 * p] - mnew);
                sc[ng][2 * p + 1] = __expf(sc[ng][2 * p + 1] - mnew);
                rs += sc[ng][2 * p] + sc[ng][2 * p + 1];
            }
            rs += __shfl_xor_sync(0xffffffffu, rs, 1);
            rs += __shfl_xor_sync(0xffffffffu, rs, 2);
            l_r[p] = l_r[p] * f + rs;
#pragma unroll
            for (int dt = 0; dt < 8; dt++) {
                oc[dt][2 * p] *= f;
                oc[dt][2 * p + 1] *= f;
            }
        }

        // ---- O += P V (P from registers; Phi*Vhi + Phi*Vlo + Plo*Vhi) ----
#pragma unroll
        for (int kk = 0; kk < 8; kk++) {
            // pack P fragments (accum layout == A-frag layout)
            uint32_t ph[4], pl[4];
#pragma unroll
            for (int u = 0; u < 2; u++) {           // u: ng = 2kk+u (k, k+8)
                const int ng = 2 * kk + u;
#pragma unroll
                for (int v = 0; v < 2; v++) {       // v: rows r, r+8
                    const float p0 = sc[ng][2 * v];
                    const float p1 = sc[ng][2 * v + 1];
                    const __nv_bfloat16 h0 = __float2bfloat16(p0);
                    const __nv_bfloat16 h1 = __float2bfloat16(p1);
                    ph[u * 2 + v] = pack_bf2(__bfloat162float(h0), __bfloat162float(h1));
                    pl[u * 2 + v] = pack_bf2(p0 - __bfloat162float(h0),
                                             p1 - __bfloat162float(h1));
                }
            }
            // wait: A-frag order is {a0=(r,k), a1=(r+8,k), a2=(r,k+8), a3=(r+8,k+8)}
            // u indexes k-half, v indexes row-half -> a[u*2+v] is correct.
            const int blk = kk >> 2, kin = kk & 3;
            const uint32_t swV = (uint32_t)(((kin * 2 + cB) ^ swz) << 4);
#pragma unroll
            for (int nt = 0; nt < 4; nt++) {
                const uint32_t voff = (uint32_t)((blk * 64 + nt * 16 +
                                     ((lane >> 4) << 3) + (lane & 7)) * 128);
                uint32_t vh[4], vl[4];
                ldm4(st + 32768 + voff + swV, vh);
                ldm4(st + 49152 + voff + swV, vl);
#pragma unroll
                for (int h2 = 0; h2 < 2; h2++) {
                    const int dt = nt * 2 + h2;
                    mma_bf16(oc[dt], ph, &vh[h2 * 2]);
                    mma_bf16(oc[dt], ph, &vl[h2 * 2]);
                    mma_bf16(oc[dt], pl, &vh[h2 * 2]);
                }
            }
        }

        __syncthreads();
        if (kt + 2 < N_ / 128) load_stage(kt & 1, kt + 2);
    }

    // ---- epilogue: O/l -> bf16 hi/lo planes in (B,N,C) layout ----
    const size_t nx = (size_t)BN_ * C_;
    const int b = bh >> 4, h = bh & 15;
#pragma unroll
    for (int p = 0; p < 2; p++) {
        const int n = q0 + wid * 16 + (lane >> 2) + 8 * p;
        const float inv = 1.f / l_r[p];
#pragma unroll
        for (int dt = 0; dt < 8; dt++) {
            const int d = dt * 8 + 2 * (lane & 3);
            const float v0 = oc[dt][2 * p] * inv;
            const float v1 = oc[dt][2 * p + 1] * inv;
            const __nv_bfloat16 h0 = __float2bfloat16(v0);
            const __nv_bfloat16 h1 = __float2bfloat16(v1);
            const size_t oi = ((size_t)(b * N_ + n)) * C_ + h * D_ + d;
            *(__nv_bfloat162*)&outs[oi] = __halves2bfloat162(h0, h1);
            *(__nv_bfloat162*)&outs[nx + oi] =
                __halves2bfloat162(__float2bfloat16(v0 - __bfloat162float(h0)),
                                   __float2bfloat16(v1 - __bfloat162float(h1)));
        }
    }
}

// =====================================================================
extern "C" void kernel_launch(void* const* d_in, const int* in_sizes, int n_in,
                              void* d_out, int out_size)
{
    const float* x      = (const float*)d_in[0];
    const float* cosd   = (const float*)d_in[1];
    const float* sind   = (const float*)d_in[2];
    const float* w_qkv  = (const float*)d_in[3];
    const float* w_proj = (const float*)d_in[4];
    const float* q_gam  = (const float*)d_in[5];
    const float* k_gam  = (const float*)d_in[6];
    float* out = (float*)d_out;

    float* p_qkv = nullptr;
    __nv_bfloat16 *p_xs = nullptr, *p_atts = nullptr, *p_wqkvs = nullptr, *p_wprojs = nullptr;
    cudaGetSymbolAddress((void**)&p_qkv, g_qkv);
    cudaGetSymbolAddress((void**)&p_xs, g_xs);
    cudaGetSymbolAddress((void**)&p_atts, g_atts);
    cudaGetSymbolAddress((void**)&p_wqkvs, g_wqkvs);
    cudaGetSymbolAddress((void**)&p_wprojs, g_wprojs);

    const size_t n_x = (size_t)BN_ * C_;
    const size_t n_wqkv = (size_t)3 * C_ * C_;
    const size_t n_wproj = (size_t)C_ * C_;

    cudaFuncSetAttribute(gemm_mma,
                         cudaFuncAttributeMaxDynamicSharedMemorySize, 2 * STG);
    cudaFuncSetAttribute(flash_mma,
                         cudaFuncAttributeMaxDynamicSharedMemorySize, FLASH_SMEM);

    // 1) split inputs to (hi,lo) bf16 planes
    split_kernel<<<(int)(n_x / 4 / 256), 256>>>(x, p_xs, n_x);
    split_kernel<<<(int)(n_wqkv / 4 / 256), 256>>>(w_qkv, p_wqkvs, n_wqkv);
    split_kernel<<<(int)(n_wproj / 4 / 256), 256>>>(w_proj, p_wprojs, n_wproj);

    // 2) QKV projection (tensor cores)
    gemm_mma<<<dim3(3 * C_ / 128, BN_ / 128), 256, 2 * STG>>>(
        p_xs, n_x, p_wqkvs, n_wqkv, p_qkv, 3 * C_, C_);

    // 3) RMSNorm + RoPE -> bf16 planes; V transpose -> bf16 planes
    prep_kernel<<<BN_, 512>>>(cosd, sind, q_gam, k_gam);
    vtrans_kernel<<<dim3(BH_, N_ / 64), 256>>>();

    // 4) flash attention on tensor cores
    flash_mma<<<dim3(N_ / 128, BH_), 256, FLASH_SMEM>>>(p_atts);

    // 5) output projection (tensor cores)
    gemm_mma<<<dim3(C_ / 128, BN_ / 128), 256, 2 * STG>>>(
        p_atts, n_x, p_wprojs, n_wproj, out, C_, C_);
}

// round 5
// speedup vs baseline: 3.2462x; 1.5411x over previous
#include <cuda_runtime.h>
#include <cuda_bf16.h>
#include <cstdint>
#include <math.h>

#define B_  4
#define N_  2048
#define C_  1024
#define H_  16
#define D_  64
#define BH_ (B_ * H_)   // 64
#define BN_ (B_ * N_)   // 8192

// ---------------- scratch (device globals; no allocations allowed) ----------
__device__ float g_qkv[(size_t)BN_ * 3 * C_];            // [b*n][3C]
__device__ __nv_bfloat16 g_xs[(size_t)2 * BN_ * C_];     // hi plane, lo plane
__device__ __nv_bfloat16 g_atts[(size_t)2 * BN_ * C_];
__device__ __nv_bfloat16 g_wqkvs[(size_t)2 * 3 * C_ * C_];
__device__ __nv_bfloat16 g_wprojs[(size_t)2 * C_ * C_];
__device__ __nv_bfloat16 g_qb[(size_t)2 * BH_ * N_ * D_];  // [2][bh][n][d], pre-scaled
__device__ __nv_bfloat16 g_kb[(size_t)2 * BH_ * N_ * D_];  // [2][bh][n][d]
__device__ __nv_bfloat16 g_vb[(size_t)2 * BH_ * D_ * N_];  // [2][bh][d][n]

#define QKP ((size_t)BH_ * N_ * D_)   // plane stride for q/k/v bf16 buffers

// =====================================================================
// helpers (family-portable PTX only: cp.async / ldmatrix / mma.sync)
// =====================================================================
__device__ __forceinline__ uint32_t smem_u32(const void* p) {
    uint32_t a;
    asm("{ .reg .u64 t; cvta.to.shared.u64 t, %1; cvt.u32.u64 %0, t; }"
        : "=r"(a) : "l"(p));
    return a;
}

__device__ __forceinline__ void cpa16(uint32_t s, const void* g) {
    asm volatile("cp.async.cg.shared.global [%0], [%1], 16;"
                 :: "r"(s), "l"(g) : "memory");
}
#define CP_COMMIT()  asm volatile("cp.async.commit_group;" ::: "memory")
#define CP_WAIT(n)   asm volatile("cp.async.wait_group %0;" :: "n"(n) : "memory")

__device__ __forceinline__ void ldm4(uint32_t addr, uint32_t* r) {
    asm volatile("ldmatrix.sync.aligned.m8n8.x4.shared.b16 {%0,%1,%2,%3}, [%4];"
                 : "=r"(r[0]), "=r"(r[1]), "=r"(r[2]), "=r"(r[3]) : "r"(addr));
}

__device__ __forceinline__ void mma_bf16(float* c, const uint32_t* a, const uint32_t* b) {
    asm volatile(
        "mma.sync.aligned.m16n8k16.row.col.f32.bf16.bf16.f32 "
        "{%0,%1,%2,%3}, {%4,%5,%6,%7}, {%8,%9}, {%0,%1,%2,%3};"
        : "+f"(c[0]), "+f"(c[1]), "+f"(c[2]), "+f"(c[3])
        : "r"(a[0]), "r"(a[1]), "r"(a[2]), "r"(a[3]), "r"(b[0]), "r"(b[1]));
}

__device__ __forceinline__ uint32_t pack_bf2(float a, float b) {
    __nv_bfloat162 t = __floats2bfloat162_rn(a, b);
    return *(uint32_t*)&t;
}

// =====================================================================
// fp32 -> (hi, lo) bf16 split planes
// =====================================================================
__global__ void split_kernel(const float* __restrict__ src,
                             __nv_bfloat16* __restrict__ dst, size_t n)
{
    size_t i = ((size_t)blockIdx.x * blockDim.x + threadIdx.x) * 4;
    if (i >= n) return;
    float4 v = *(const float4*)(src + i);
    __nv_bfloat16 h0 = __float2bfloat16(v.x);
    __nv_bfloat16 h1 = __float2bfloat16(v.y);
    __nv_bfloat16 h2 = __float2bfloat16(v.z);
    __nv_bfloat16 h3 = __float2bfloat16(v.w);
    __nv_bfloat162* hp = (__nv_bfloat162*)(dst + i);
    hp[0] = __halves2bfloat162(h0, h1);
    hp[1] = __halves2bfloat162(h2, h3);
    __nv_bfloat162* lp = (__nv_bfloat162*)(dst + n + i);
    lp[0] = __halves2bfloat162(__float2bfloat16(v.x - __bfloat162float(h0)),
                               __float2bfloat16(v.y - __bfloat162float(h1)));
    lp[1] = __halves2bfloat162(__float2bfloat16(v.z - __bfloat162float(h2)),
                               __float2bfloat16(v.w - __bfloat162float(h3)));
}

// =====================================================================
// bf16x3 GEMM on mma.sync: C = A[M,K]*B[N,K]^T  (3-stage cp.async pipeline)
// smem: 3 stages x (Ahi|Alo|Bhi|Blo each [128][64]) = 3 x 64KB = 192KB
// =====================================================================
#define STG 65536
#define GSMEM (3 * STG)
__global__ __launch_bounds__(256, 1)
void gemm_mma(const __nv_bfloat16* __restrict__ A, size_t planeA,
              const __nv_bfloat16* __restrict__ Bm, size_t planeB,
              float* __restrict__ C, int ldC, int K)
{
    extern __shared__ char smem[];
    const uint32_t sb = smem_u32(smem);
    const int tid  = threadIdx.x;
    const int lane = tid & 31;
    const int wid  = tid >> 5;
    const int m0 = blockIdx.y * 128;
    const int n0 = blockIdx.x * 128;
    const int wm = (wid >> 2) * 64;
    const int wn = (wid & 3) * 32;

    int lrow[4], lc[4];
    uint32_t lsoff[4];
#pragma unroll
    for (int j = 0; j < 4; j++) {
        int idx = tid + 256 * j;
        lrow[j] = idx >> 3;
        lc[j] = idx & 7;
        lsoff[j] = (uint32_t)(lrow[j] * 128 + ((lc[j] ^ (lrow[j] & 7)) << 4));
    }

    uint32_t arow[4], brow[2];
#pragma unroll
    for (int mt = 0; mt < 4; mt++) arow[mt] = (uint32_t)((wm + mt * 16 + (lane & 15)) * 128);
#pragma unroll
    for (int nt = 0; nt < 2; nt++)
        brow[nt] = (uint32_t)((wn + nt * 16 + ((lane >> 4) << 3) + (lane & 7)) * 128);
    const int swz = lane & 7;
    const int cA = lane >> 4;
    const int cB = (lane >> 3) & 1;

    float acc[4][4][4];
#pragma unroll
    for (int i = 0; i < 4; i++)
#pragma unroll
        for (int j = 0; j < 4; j++)
#pragma unroll
            for (int r = 0; r < 4; r++) acc[i][j][r] = 0.f;

    const int KT = K >> 6;

    auto load_stage = [&](int buf, int kt) {
        const uint32_t st = sb + buf * STG;
        const int k0 = kt * 64;
#pragma unroll
        for (int j = 0; j < 4; j++) {
            const __nv_bfloat16* ga = A + (size_t)(m0 + lrow[j]) * K + k0 + lc[j] * 8;
            cpa16(st + lsoff[j], ga);
            cpa16(st + 16384 + lsoff[j], ga + planeA);
            const __nv_bfloat16* gb = Bm + (size_t)(n0 + lrow[j]) * K + k0 + lc[j] * 8;
            cpa16(st + 32768 + lsoff[j], gb);
            cpa16(st + 49152 + lsoff[j], gb + planeB);
        }
        CP_COMMIT();
    };

    load_stage(0, 0);
    load_stage(1, 1);
    load_stage(2, 2);

#pragma unroll 1
    for (int kt = 0; kt < KT; kt++) {
        if (kt + 2 < KT)      { CP_WAIT(2); }
        else if (kt + 1 < KT) { CP_WAIT(1); }
        else                  { CP_WAIT(0); }
        __syncthreads();

        const uint32_t st = sb + (kt % 3) * STG;
#pragma unroll
        for (int kk = 0; kk < 4; kk++) {
            uint32_t ah[4][4], al[4][4], bh[2][4], bl[2][4];
            const uint32_t swA = (uint32_t)(((kk * 2 + cA) ^ swz) << 4);
            const uint32_t swB = (uint32_t)(((kk * 2 + cB) ^ swz) << 4);
#pragma unroll
            for (int mt = 0; mt < 4; mt++) {
                ldm4(st + arow[mt] + swA, ah[mt]);
                ldm4(st + 16384 + arow[mt] + swA, al[mt]);
            }
#pragma unroll
            for (int nt = 0; nt < 2; nt++) {
                ldm4(st + 32768 + brow[nt] + swB, bh[nt]);
                ldm4(st + 49152 + brow[nt] + swB, bl[nt]);
            }
#pragma unroll
            for (int mt = 0; mt < 4; mt++)
#pragma unroll
                for (int nt = 0; nt < 2; nt++)
#pragma unroll
                    for (int h = 0; h < 2; h++) {
                        const int ng = nt * 2 + h;
                        mma_bf16(acc[mt][ng], ah[mt], &bh[nt][h * 2]);
                        mma_bf16(acc[mt][ng], ah[mt], &bl[nt][h * 2]);
                        mma_bf16(acc[mt][ng], al[mt], &bh[nt][h * 2]);
                    }
        }
        __syncthreads();
        if (kt + 3 < KT) load_stage(kt % 3, kt + 3);
    }

    const int g = lane >> 2, tg = lane & 3;
#pragma unroll
    for (int mt = 0; mt < 4; mt++)
#pragma unroll
        for (int ng = 0; ng < 4; ng++) {
            const int row = m0 + wm + mt * 16 + g;
            const int col = n0 + wn + ng * 8 + tg * 2;
            *(float2*)&C[(size_t)row * ldC + col] =
                make_float2(acc[mt][ng][0], acc[mt][ng][1]);
            *(float2*)&C[(size_t)(row + 8) * ldC + col] =
                make_float2(acc[mt][ng][2], acc[mt][ng][3]);
        }
}

// =====================================================================
// Prep: RMSNorm + RoPE -> bf16 hi/lo planes [bh][n][d].
// q pre-scaled by (1/sqrt(D)) * log2(e) so flash can use exp2f.
// =====================================================================
__global__ void prep_kernel(const float* __restrict__ cosd,
                            const float* __restrict__ sind,
                            const float* __restrict__ qg,
                            const float* __restrict__ kg)
{
    const int bn = blockIdx.x;
    const int n  = bn & (N_ - 1);
    const int b  = bn >> 11;
    const int w  = threadIdx.x >> 5;
    const int l  = threadIdx.x & 31;
    const int d0 = l * 2;

    const float* base = g_qkv + (size_t)bn * (3 * C_) + w * D_ + d0;
    float2 q = *(const float2*)(base);
    float2 k = *(const float2*)(base + C_);

    float sq = q.x * q.x + q.y * q.y;
    float sk = k.x * k.x + k.y * k.y;
#pragma unroll
    for (int ofs = 16; ofs >= 1; ofs >>= 1) {
        sq += __shfl_xor_sync(0xffffffffu, sq, ofs);
        sk += __shfl_xor_sync(0xffffffffu, sk, ofs);
    }
    const float rq = rsqrtf(sq * (1.f / 64.f) + 1e-6f);
    const float rk = rsqrtf(sk * (1.f / 64.f) + 1e-6f);

    float2 gq = *(const float2*)(qg + d0);
    float2 gk = *(const float2*)(kg + d0);
    const float qa = q.x * rq * gq.x, qb = q.y * rq * gq.y;
    const float ka = k.x * rk * gk.x, kb = k.y * rk * gk.y;

    const float QS = 0.125f * 1.4426950408889634f;  // 1/sqrt(D) * log2(e)
    float2 c = *(const float2*)(cosd + n * D_ + d0);
    float2 s = *(const float2*)(sind + n * D_ + d0);
    const float qo0 = (qa * c.x - qb * s.x) * QS;
    const float qo1 = (qb * c.y + qa * s.y) * QS;
    const float ko0 = ka * c.x - kb * s.x;
    const float ko1 = kb * c.y + ka * s.y;

    const int bh = b * H_ + w;
    const size_t qi = ((size_t)bh * N_ + n) * D_ + d0;

    __nv_bfloat16 qh0 = __float2bfloat16(qo0), qh1 = __float2bfloat16(qo1);
    *(__nv_bfloat162*)&g_qb[qi] = __halves2bfloat162(qh0, qh1);
    *(__nv_bfloat162*)&g_qb[QKP + qi] =
        __halves2bfloat162(__float2bfloat16(qo0 - __bfloat162float(qh0)),
                           __float2bfloat16(qo1 - __bfloat162float(qh1)));
    __nv_bfloat16 kh0 = __float2bfloat16(ko0), kh1 = __float2bfloat16(ko1);
    *(__nv_bfloat162*)&g_kb[qi] = __halves2bfloat162(kh0, kh1);
    *(__nv_bfloat162*)&g_kb[QKP + qi] =
        __halves2bfloat162(__float2bfloat16(ko0 - __bfloat162float(kh0)),
                           __float2bfloat16(ko1 - __bfloat162float(kh1)));
}

// =====================================================================
// V transpose: g_qkv v-part [b][n][h*64+d] -> g_vb [2][bh][d][n] bf16 hi/lo
// =====================================================================
__global__ void vtrans_kernel()
{
    __shared__ float t[64][65];
    const int bh = blockIdx.x;
    const int n0 = blockIdx.y * 64;
    const int b = bh >> 4, h = bh & 15;
    const int tid = threadIdx.x;

    for (int i = tid; i < 4096; i += 256) {
        const int r = i >> 6, c = i & 63;
        t[c][r] = g_qkv[((size_t)(b * N_ + n0 + r)) * (3 * C_) + 2 * C_ + h * 64 + c];
    }
    __syncthreads();
    for (int i = tid; i < 4096; i += 256) {
        const int d = i >> 6, n = i & 63;
        const float v = t[d][n];
        const __nv_bfloat16 hv = __float2bfloat16(v);
        const size_t oi = ((size_t)bh * D_ + d) * N_ + n0 + n;
        g_vb[oi] = hv;
        g_vb[QKP + oi] = __float2bfloat16(v - __bfloat162float(hv));
    }
}

// =====================================================================
// Flash attention on tensor cores (bf16x3), 3-stage cp.async pipeline.
// smem: Qhi|Qlo [128][64] (32 KB) + 3 stages of Khi|Klo|Vhi|Vlo (64 KB)
//     = 224 KB.
// =====================================================================
#define FSTG 65536
#define FLASH_SMEM (32768 + 3 * FSTG)

__global__ __launch_bounds__(256, 1)
void flash_mma(__nv_bfloat16* __restrict__ outs)
{
    extern __shared__ char smem[];
    const uint32_t sb = smem_u32(smem);
    const int bh  = blockIdx.y;
    const int q0  = blockIdx.x * 128;
    const int tid = threadIdx.x;
    const int lane = tid & 31;
    const int wid  = tid >> 5;

    const __nv_bfloat16* qbp = g_qb + (size_t)bh * N_ * D_;
    const __nv_bfloat16* kbp = g_kb + (size_t)bh * N_ * D_;
    const __nv_bfloat16* vbp = g_vb + (size_t)bh * D_ * N_;

    int lrow[4], lc[4];
    uint32_t lsoff[4];
#pragma unroll
    for (int j = 0; j < 4; j++) {
        int idx = tid + 256 * j;
        lrow[j] = idx >> 3;
        lc[j] = idx & 7;
        lsoff[j] = (uint32_t)(lrow[j] * 128 + ((lc[j] ^ (lrow[j] & 7)) << 4));
    }

    // Q tile (resident): folded into the first commit group
#pragma unroll
    for (int j = 0; j < 4; j++) {
        const __nv_bfloat16* gq = qbp + (size_t)(q0 + lrow[j]) * D_ + lc[j] * 8;
        cpa16(sb + lsoff[j], gq);
        cpa16(sb + 16384 + lsoff[j], gq + QKP);
    }

    auto load_stage = [&](int buf, int kt) {
        const uint32_t st = sb + 32768 + buf * FSTG;
        const int kc0 = kt * 128;
#pragma unroll
        for (int j = 0; j < 4; j++) {
            const __nv_bfloat16* gk = kbp + (size_t)(kc0 + lrow[j]) * D_ + lc[j] * 8;
            cpa16(st + lsoff[j], gk);
            cpa16(st + 16384 + lsoff[j], gk + QKP);
            const int blk = lrow[j] >> 6, d = lrow[j] & 63;
            const __nv_bfloat16* gv = vbp + (size_t)d * N_ + kc0 + blk * 64 + lc[j] * 8;
            cpa16(st + 32768 + lsoff[j], gv);
            cpa16(st + 49152 + lsoff[j], gv + QKP);
        }
        CP_COMMIT();
    };

    load_stage(0, 0);
    load_stage(1, 1);
    load_stage(2, 2);

    const int swz = lane & 7;
    const int cA = lane >> 4;
    const int cB = (lane >> 3) & 1;
    const uint32_t aoff = (uint32_t)((wid * 16 + (lane & 15)) * 128);
    uint32_t boff[8];
#pragma unroll
    for (int nt = 0; nt < 8; nt++)
        boff[nt] = (uint32_t)((nt * 16 + ((lane >> 4) << 3) + (lane & 7)) * 128);

    float oc[8][4];
    float m_r[2], l_r[2];
#pragma unroll
    for (int i = 0; i < 8; i++)
#pragma unroll
        for (int j = 0; j < 4; j++) oc[i][j] = 0.f;
    m_r[0] = m_r[1] = -1e30f;
    l_r[0] = l_r[1] = 0.f;

    const int KTN = N_ / 128;
#pragma unroll 1
    for (int kt = 0; kt < KTN; kt++) {
        if (kt + 2 < KTN)      { CP_WAIT(2); }
        else if (kt + 1 < KTN) { CP_WAIT(1); }
        else                   { CP_WAIT(0); }
        __syncthreads();
        const uint32_t st = sb + 32768 + (kt % 3) * FSTG;

        // ---- S = Q K^T (3-pass bf16x3); S already in log2 units ----
        float sc[16][4];
#pragma unroll
        for (int i = 0; i < 16; i++)
#pragma unroll
            for (int j = 0; j < 4; j++) sc[i][j] = 0.f;

#pragma unroll
        for (int kk = 0; kk < 4; kk++) {
            const uint32_t swA = (uint32_t)(((kk * 2 + cA) ^ swz) << 4);
            const uint32_t swB = (uint32_t)(((kk * 2 + cB) ^ swz) << 4);
            uint32_t aq[4], aql[4];
            ldm4(sb + aoff + swA, aq);
            ldm4(sb + 16384 + aoff + swA, aql);
#pragma unroll
            for (int nt = 0; nt < 8; nt++) {
                uint32_t kh[4], kl[4];
                ldm4(st + boff[nt] + swB, kh);
                ldm4(st + 16384 + boff[nt] + swB, kl);
#pragma unroll
                for (int h = 0; h < 2; h++) {
                    const int ng = nt * 2 + h;
                    mma_bf16(sc[ng], aq, &kh[h * 2]);
                    mma_bf16(sc[ng], aq, &kl[h * 2]);
                    mma_bf16(sc[ng], aql, &kh[h * 2]);
                }
            }
        }

        // ---- online softmax in log2 domain (exp2f = raw MUFU.EX2) ----
#pragma unroll
        for (int p = 0; p < 2; p++) {
            float mx = -1e30f;
#pragma unroll
            for (int ng = 0; ng < 16; ng++)
                mx = fmaxf(mx, fmaxf(sc[ng][2 * p], sc[ng][2 * p + 1]));
            mx = fmaxf(mx, __shfl_xor_sync(0xffffffffu, mx, 1));
            mx = fmaxf(mx, __shfl_xor_sync(0xffffffffu, mx, 2));
            const float mnew = fmaxf(m_r[p], mx);
            const float f = exp2f(m_r[p] - mnew);
            m_r[p] = mnew;
            float rs = 0.f;
#pragma unroll
            for (int ng = 0; ng < 16; ng++) {
                sc[ng][2 * p]     = exp2f(sc[ng][2 * p] - mnew);
                sc[ng][2 * p + 1] = exp2f(sc[ng][2 * p + 1] - mnew);
                rs += sc[ng][2 * p] + sc[ng][2 * p + 1];
            }
            rs += __shfl_xor_sync(0xffffffffu, rs, 1);
            rs += __shfl_xor_sync(0xffffffffu, rs, 2);
            l_r[p] = l_r[p] * f + rs;
#pragma unroll
            for (int dt = 0; dt < 8; dt++) {
                oc[dt][2 * p] *= f;
                oc[dt][2 * p + 1] *= f;
            }
        }

        // ---- O += P V (Phi*Vhi + Phi*Vlo + Plo*Vhi) ----
#pragma unroll
        for (int kk = 0; kk < 8; kk++) {
            uint32_t ph[4], pl[4];
#pragma unroll
            for (int u = 0; u < 2; u++) {
                const int ng = 2 * kk + u;
#pragma unroll
                for (int v = 0; v < 2; v++) {
                    const float p0 = sc[ng][2 * v];
                    const float p1 = sc[ng][2 * v + 1];
                    const __nv_bfloat16 h0 = __float2bfloat16(p0);
                    const __nv_bfloat16 h1 = __float2bfloat16(p1);
                    ph[u * 2 + v] = pack_bf2(__bfloat162float(h0), __bfloat162float(h1));
                    pl[u * 2 + v] = pack_bf2(p0 - __bfloat162float(h0),
                                             p1 - __bfloat162float(h1));
                }
            }
            const int blk = kk >> 2, kin = kk & 3;
            const uint32_t swV = (uint32_t)(((kin * 2 + cB) ^ swz) << 4);
#pragma unroll
            for (int nt = 0; nt < 4; nt++) {
                const uint32_t voff = (uint32_t)((blk * 64 + nt * 16 +
                                     ((lane >> 4) << 3) + (lane & 7)) * 128);
                uint32_t vh[4], vl[4];
                ldm4(st + 32768 + voff + swV, vh);
                ldm4(st + 49152 + voff + swV, vl);
#pragma unroll
                for (int h2 = 0; h2 < 2; h2++) {
                    const int dt = nt * 2 + h2;
                    mma_bf16(oc[dt], ph, &vh[h2 * 2]);
                    mma_bf16(oc[dt], ph, &vl[h2 * 2]);
                    mma_bf16(oc[dt], pl, &vh[h2 * 2]);
                }
            }
        }

        __syncthreads();
        if (kt + 3 < KTN) load_stage(kt % 3, kt + 3);
    }

    // ---- epilogue: O/l -> bf16 hi/lo planes in (B,N,C) layout ----
    const size_t nx = (size_t)BN_ * C_;
    const int b = bh >> 4, h = bh & 15;
#pragma unroll
    for (int p = 0; p < 2; p++) {
        const int n = q0 + wid * 16 + (lane >> 2) + 8 * p;
        const float inv = 1.f / l_r[p];
#pragma unroll
        for (int dt = 0; dt < 8; dt++) {
            const int d = dt * 8 + 2 * (lane & 3);
            const float v0 = oc[dt][2 * p] * inv;
            const float v1 = oc[dt][2 * p + 1] * inv;
            const __nv_bfloat16 h0 = __float2bfloat16(v0);
            const __nv_bfloat16 h1 = __float2bfloat16(v1);
            const size_t oi = ((size_t)(b * N_ + n)) * C_ + h * D_ + d;
            *(__nv_bfloat162*)&outs[oi] = __halves2bfloat162(h0, h1);
            *(__nv_bfloat162*)&outs[nx + oi] =
                __halves2bfloat162(__float2bfloat16(v0 - __bfloat162float(h0)),
                                   __float2bfloat16(v1 - __bfloat162float(h1)));
        }
    }
}

// =====================================================================
extern "C" void kernel_launch(void* const* d_in, const int* in_sizes, int n_in,
                              void* d_out, int out_size)
{
    const float* x      = (const float*)d_in[0];
    const float* cosd   = (const float*)d_in[1];
    const float* sind   = (const float*)d_in[2];
    const float* w_qkv  = (const float*)d_in[3];
    const float* w_proj = (const float*)d_in[4];
    const float* q_gam  = (const float*)d_in[5];
    const float* k_gam  = (const float*)d_in[6];
    float* out = (float*)d_out;

    float* p_qkv = nullptr;
    __nv_bfloat16 *p_xs = nullptr, *p_atts = nullptr, *p_wqkvs = nullptr, *p_wprojs = nullptr;
    cudaGetSymbolAddress((void**)&p_qkv, g_qkv);
    cudaGetSymbolAddress((void**)&p_xs, g_xs);
    cudaGetSymbolAddress((void**)&p_atts, g_atts);
    cudaGetSymbolAddress((void**)&p_wqkvs, g_wqkvs);
    cudaGetSymbolAddress((void**)&p_wprojs, g_wprojs);

    const size_t n_x = (size_t)BN_ * C_;
    const size_t n_wqkv = (size_t)3 * C_ * C_;
    const size_t n_wproj = (size_t)C_ * C_;

    cudaFuncSetAttribute(gemm_mma,
                         cudaFuncAttributeMaxDynamicSharedMemorySize, GSMEM);
    cudaFuncSetAttribute(flash_mma,
                         cudaFuncAttributeMaxDynamicSharedMemorySize, FLASH_SMEM);

    // 1) split inputs to (hi,lo) bf16 planes
    split_kernel<<<(int)(n_x / 4 / 256), 256>>>(x, p_xs, n_x);
    split_kernel<<<(int)(n_wqkv / 4 / 256), 256>>>(w_qkv, p_wqkvs, n_wqkv);
    split_kernel<<<(int)(n_wproj / 4 / 256), 256>>>(w_proj, p_wprojs, n_wproj);

    // 2) QKV projection (tensor cores)
    gemm_mma<<<dim3(3 * C_ / 128, BN_ / 128), 256, GSMEM>>>(
        p_xs, n_x, p_wqkvs, n_wqkv, p_qkv, 3 * C_, C_);

    // 3) RMSNorm + RoPE -> bf16 planes; V transpose -> bf16 planes
    prep_kernel<<<BN_, 512>>>(cosd, sind, q_gam, k_gam);
    vtrans_kernel<<<dim3(BH_, N_ / 64), 256>>>();

    // 4) flash attention on tensor cores
    flash_mma<<<dim3(N_ / 128, BH_), 256, FLASH_SMEM>>>(p_atts);

    // 5) output projection (tensor cores)
    gemm_mma<<<dim3(C_ / 128, BN_ / 128), 256, GSMEM>>>(
        p_atts, n_x, p_wprojs, n_wproj, out, C_, C_);
}